// round 13
// baseline (speedup 1.0000x reference)
#include <cuda_runtime.h>
#include <cuda_bf16.h>
#include <stdint.h>
#include <math.h>

// Problem constants
#define Bz  2
#define Sq  2048
#define Dm  1024
#define Hn  16
#define DHd 64
#define BH  (Bz * Hn)
#define NIN ((size_t)Bz * Sq * Dm)
#define CLOG2E 1.4426950408889634f

// ---------------------------------------------------------------------------
// Scratch (allocation-free __device__ globals)
// ---------------------------------------------------------------------------
__device__ __align__(256) float g_q[(size_t)BH * Sq * DHd];
__device__ __align__(256) float g_k[(size_t)BH * Sq * DHd];
__device__ __align__(256) float g_v[(size_t)BH * Sq * DHd];
__device__ __align__(256) float g_cpart[2 * NIN];
__device__ int g_mask_is_int;

// ---------------------------------------------------------------------------
// Helpers
// ---------------------------------------------------------------------------
__device__ __forceinline__ uint32_t smem_u32(const void* p) {
    return (uint32_t)__cvta_generic_to_shared(p);
}
__device__ __forceinline__ void ldm4(uint32_t* r, uint32_t a) {
    asm volatile("ldmatrix.sync.aligned.m8n8.x4.shared.b16 {%0,%1,%2,%3},[%4];"
                 : "=r"(r[0]), "=r"(r[1]), "=r"(r[2]), "=r"(r[3]) : "r"(a));
}
__device__ __forceinline__ void ldm4t(uint32_t* r, uint32_t a) {
    asm volatile("ldmatrix.sync.aligned.m8n8.x4.trans.shared.b16 {%0,%1,%2,%3},[%4];"
                 : "=r"(r[0]), "=r"(r[1]), "=r"(r[2]), "=r"(r[3]) : "r"(a));
}
__device__ __forceinline__ void mma_bf16(float* c, const uint32_t* a, const uint32_t* b) {
    asm volatile(
        "mma.sync.aligned.m16n8k16.row.col.f32.bf16.bf16.f32 "
        "{%0,%1,%2,%3},{%4,%5,%6,%7},{%8,%9},{%0,%1,%2,%3};"
        : "+f"(c[0]), "+f"(c[1]), "+f"(c[2]), "+f"(c[3])
        : "r"(a[0]), "r"(a[1]), "r"(a[2]), "r"(a[3]), "r"(b[0]), "r"(b[1]));
}
// RN-based split (proven: rel_err ~2e-5)
__device__ __forceinline__ void split1(float x, __nv_bfloat16& h, __nv_bfloat16& l) {
    h = __float2bfloat16(x);
    l = __float2bfloat16(x - __bfloat162float(h));
}
__device__ __forceinline__ void split_to(float4 v, __nv_bfloat16* dh, __nv_bfloat16* dl) {
    __nv_bfloat16 h0, h1, h2, h3, l0, l1, l2, l3;
    split1(v.x, h0, l0); split1(v.y, h1, l1);
    split1(v.z, h2, l2); split1(v.w, h3, l3);
    *(__nv_bfloat162*)(dh)     = __nv_bfloat162{h0, h1};
    *(__nv_bfloat162*)(dh + 2) = __nv_bfloat162{h2, h3};
    *(__nv_bfloat162*)(dl)     = __nv_bfloat162{l0, l1};
    *(__nv_bfloat162*)(dl + 2) = __nv_bfloat162{l2, l3};
}
__device__ __forceinline__ float ex2(float x) {
    float y; asm("ex2.approx.f32 %0,%1;" : "=f"(y) : "f"(x)); return y;
}
#define CP16(dst, src) \
    asm volatile("cp.async.cg.shared.global [%0], [%1], 16;" \
                 :: "r"(dst), "l"(src) : "memory")
#define CP_COMMIT() asm volatile("cp.async.commit_group;" ::: "memory")
#define CP_WAIT1()  asm volatile("cp.async.wait_group 1;" ::: "memory")
#define CP_WAIT0()  asm volatile("cp.async.wait_group 0;" ::: "memory")

// ---------------------------------------------------------------------------
// Mask dtype detector
// ---------------------------------------------------------------------------
__global__ void detect_mask_kernel(const unsigned char* __restrict__ m) {
    __shared__ int any;
    if (threadIdx.x == 0) any = 0;
    __syncthreads();
    int local = 0;
    for (int i = threadIdx.x; i < Bz * Sq; i += blockDim.x)
        if ((i & 3) && m[i]) local = 1;
    if (local) atomicOr(&any, 1);
    __syncthreads();
    if (threadIdx.x == 0) g_mask_is_int = (any == 0) ? 1 : 0;
}

// ---------------------------------------------------------------------------
// Projection GEMM — R12 body. MODE 1 additionally fuses the ctx-partial
// reduce: A = staged partial0 + L2-resident LDG of partial1 (A2).
// ---------------------------------------------------------------------------
struct ProjArgs {
    const float* A[3]; const float* A2[3];
    const float* W[3]; const float* bias[3]; float* C[3];
};
#define SM_PROJ 107520

template <int MODE>
__global__ void __launch_bounds__(256) proj_gemm(ProjArgs args)
{
    constexpr int SA = 40, SB = 136;
    extern __shared__ char smc[];
    float* Ar = (float*)smc;
    float* Br = (float*)(smc + 36864);
    __nv_bfloat16* Ah = (__nv_bfloat16*)(smc + 69632);
    __nv_bfloat16* Al = (__nv_bfloat16*)(smc + 79872);
    __nv_bfloat16* Bh = (__nv_bfloat16*)(smc + 90112);
    __nv_bfloat16* Bl = (__nv_bfloat16*)(smc + 98816);

    const int z = blockIdx.z;
    const float* A = args.A[z];
    const float* A2 = args.A2[z];
    const float* W = args.W[z];
    const float* bias = args.bias[z];
    float* C = args.C[z];

    const int tid = threadIdx.x, lane = tid & 31, warp = tid >> 5;
    const int wm = (warp >> 2) * 64;
    const int wn = (warp & 3) * 32;
    const int bm = blockIdx.y * 128;
    const int bn = blockIdx.x * 128;

    float acc[4][4][4];
#pragma unroll
    for (int i = 0; i < 4; i++)
#pragma unroll
        for (int j = 0; j < 4; j++)
#pragma unroll
            for (int q = 0; q < 4; q++) acc[i][j][q] = 0.f;

    const uint32_t aH = smem_u32(Ah), aL = smem_u32(Al);
    const uint32_t bH = smem_u32(Bh), bL = smem_u32(Bl);

    auto issue = [&](int s, int k0) {
        float* ArS = Ar + s * (128 * 36);
        float* BrS = Br + s * (32 * 128);
#pragma unroll
        for (int r = 0; r < 4; r++) {
            const int idx = tid + r * 256;
            const int row = idx >> 3, ch = (idx & 7) * 4;
            CP16(smem_u32(ArS + row * 36 + ch),
                 A + (size_t)(bm + row) * Dm + k0 + ch);
        }
#pragma unroll
        for (int r = 0; r < 4; r++) {
            const int idx = tid + r * 256;
            const int row = idx >> 5, ch = (idx & 31) * 4;
            CP16(smem_u32(BrS + row * 128 + ch),
                 W + (size_t)(k0 + row) * Dm + bn + ch);
        }
        CP_COMMIT();
    };

    issue(0, 0);
    for (int it = 0; it < Dm / 32; ++it) {
        const int s = it & 1;
        if (it + 1 < Dm / 32) { issue(s ^ 1, (it + 1) * 32); CP_WAIT1(); }
        else                  { CP_WAIT0(); }
        __syncthreads();

        float* ArS = Ar + s * (128 * 36);
        float* BrS = Br + s * (32 * 128);
#pragma unroll
        for (int r = 0; r < 4; r++) {
            const int m  = (tid >> 3) + r * 32;
            const int kq = (tid & 7) * 4;
            float4 v = *(const float4*)(ArS + m * 36 + kq);
            if (MODE == 1) {
                // fused ctx-partial reduce: add L2-resident partial1
                float4 w = *(const float4*)(A2 + (size_t)(bm + m) * Dm + it * 32 + kq);
                v.x += w.x; v.y += w.y; v.z += w.z; v.w += w.w;
            }
            split_to(v, &Ah[m * SA + kq], &Al[m * SA + kq]);
        }
#pragma unroll
        for (int r = 0; r < 4; r++) {
            const int kr = (tid >> 5) + r * 8;
            const int n4 = (tid & 31) * 4;
            float4 v = *(const float4*)(BrS + kr * 128 + n4);
            split_to(v, &Bh[kr * SB + n4], &Bl[kr * SB + n4]);
        }
        __syncthreads();

#pragma unroll
        for (int kk = 0; kk < 32; kk += 16) {
            uint32_t ah[4][4], al[4][4];
            const int arow = wm + (lane & 7) + ((lane >> 3) & 1) * 8;
            const int acol = kk + (lane >> 4) * 8;
#pragma unroll
            for (int mt = 0; mt < 4; mt++) {
                const uint32_t off = (uint32_t)(((arow + mt * 16) * SA + acol) * 2);
                ldm4(ah[mt], aH + off);
                ldm4(al[mt], aL + off);
            }
            uint32_t bh[4][2], bl[4][2];
            const int brow = kk + (lane & 7) + ((lane >> 3) & 1) * 8;
#pragma unroll
            for (int sp = 0; sp < 2; sp++) {
                const int bcol = wn + sp * 16 + (lane >> 4) * 8;
                const uint32_t off = (uint32_t)((brow * SB + bcol) * 2);
                uint32_t t[4];
                ldm4t(t, bH + off);
                bh[2 * sp][0] = t[0]; bh[2 * sp][1] = t[1];
                bh[2 * sp + 1][0] = t[2]; bh[2 * sp + 1][1] = t[3];
                ldm4t(t, bL + off);
                bl[2 * sp][0] = t[0]; bl[2 * sp][1] = t[1];
                bl[2 * sp + 1][0] = t[2]; bl[2 * sp + 1][1] = t[3];
            }
#pragma unroll
            for (int mt = 0; mt < 4; mt++)
#pragma unroll
                for (int nt = 0; nt < 4; nt++) {
                    mma_bf16(acc[mt][nt], ah[mt], bh[nt]);
                    mma_bf16(acc[mt][nt], ah[mt], bl[nt]);
                    mma_bf16(acc[mt][nt], al[mt], bh[nt]);
                }
        }
    }

    const int g = lane >> 2, t2 = (lane & 3) * 2;
#pragma unroll
    for (int mt = 0; mt < 4; mt++)
#pragma unroll
        for (int nt = 0; nt < 4; nt++) {
            const int col = bn + wn + nt * 8 + t2;
#pragma unroll
            for (int h2 = 0; h2 < 2; h2++) {
                const int row = bm + wm + mt * 16 + g + h2 * 8;
                float c0 = acc[mt][nt][h2 * 2 + 0] + bias[col];
                float c1 = acc[mt][nt][h2 * 2 + 1] + bias[col + 1];
                if (MODE == 0) {
                    const int bb = row >> 11, ss = row & (Sq - 1);
                    const int hh = col >> 6,  dh = col & (DHd - 1);
                    *(float2*)(C + (((size_t)(bb * Hn + hh)) * Sq + ss) * DHd + dh)
                        = make_float2(c0, c1);
                } else {
                    *(float2*)(C + (size_t)row * Dm + col) = make_float2(c0, c1);
                }
            }
        }
}

// ---------------------------------------------------------------------------
// Scores — R12 exact.
// ---------------------------------------------------------------------------
__global__ void __launch_bounds__(256) scores_kernel(
    const void* __restrict__ mask, float* __restrict__ attn)
{
    constexpr int SA = 40, SB = 40;
    __shared__ __nv_bfloat16 Ah[128 * SA], Al[128 * SA];
    __shared__ __nv_bfloat16 Bh[128 * SB], Bl[128 * SB];

    const int z = blockIdx.z, zb = z / Hn;
    const float* q = g_q + (size_t)z * Sq * DHd;
    const float* k = g_k + (size_t)z * Sq * DHd;

    const int tid = threadIdx.x, lane = tid & 31, warp = tid >> 5;
    const int wm = (warp >> 2) * 64;
    const int wn = (warp & 3) * 32;
    const int bm = blockIdx.y * 128;
    const int bn = blockIdx.x * 128;

    float acc[4][4][4];
#pragma unroll
    for (int i = 0; i < 4; i++)
#pragma unroll
        for (int j = 0; j < 4; j++)
#pragma unroll
            for (int q2 = 0; q2 < 4; q2++) acc[i][j][q2] = 0.f;

    const uint32_t aH = smem_u32(Ah), aL = smem_u32(Al);
    const uint32_t bH = smem_u32(Bh), bL = smem_u32(Bl);

    for (int k0 = 0; k0 < DHd; k0 += 32) {
#pragma unroll
        for (int r = 0; r < 4; r++) {
            const int m  = (tid >> 3) + r * 32;
            const int kq = (tid & 7) * 4;
            float4 a = *(const float4*)(q + (size_t)(bm + m) * DHd + k0 + kq);
            split_to(a, &Ah[m * SA + kq], &Al[m * SA + kq]);
            float4 b = *(const float4*)(k + (size_t)(bn + m) * DHd + k0 + kq);
            split_to(b, &Bh[m * SB + kq], &Bl[m * SB + kq]);
        }
        __syncthreads();

#pragma unroll
        for (int kk = 0; kk < 32; kk += 16) {
            uint32_t ah[4][4], al[4][4];
            const int arow = wm + (lane & 7) + ((lane >> 3) & 1) * 8;
            const int acol = kk + (lane >> 4) * 8;
#pragma unroll
            for (int mt = 0; mt < 4; mt++) {
                const uint32_t off = (uint32_t)(((arow + mt * 16) * SA + acol) * 2);
                ldm4(ah[mt], aH + off);
                ldm4(al[mt], aL + off);
            }
            uint32_t bh[4][2], bl[4][2];
#pragma unroll
            for (int sp = 0; sp < 2; sp++) {
                const int brow = wn + sp * 16 + (lane & 7) + ((lane >> 3) & 1) * 8;
                const int bcol = kk + (lane >> 4) * 8;
                const uint32_t off = (uint32_t)((brow * SB + bcol) * 2);
                uint32_t t[4];
                ldm4(t, bH + off);
                bh[2 * sp][0] = t[0]; bh[2 * sp + 1][0] = t[1];
                bh[2 * sp][1] = t[2]; bh[2 * sp + 1][1] = t[3];
                ldm4(t, bL + off);
                bl[2 * sp][0] = t[0]; bl[2 * sp + 1][0] = t[1];
                bl[2 * sp][1] = t[2]; bl[2 * sp + 1][1] = t[3];
            }
#pragma unroll
            for (int mt = 0; mt < 4; mt++)
#pragma unroll
                for (int nt = 0; nt < 4; nt++) {
                    mma_bf16(acc[mt][nt], ah[mt], bh[nt]);
                    mma_bf16(acc[mt][nt], ah[mt], bl[nt]);
                    mma_bf16(acc[mt][nt], al[mt], bh[nt]);
                }
        }
        __syncthreads();
    }

    const int g = lane >> 2, t2 = (lane & 3) * 2;
    const int mint = g_mask_is_int;
    const float NEG_INF = __int_as_float(0xff800000);
#pragma unroll
    for (int nt = 0; nt < 4; nt++) {
        const int col = bn + wn + nt * 8 + t2;
        bool m0, m1;
        if (mint) {
            m0 = ((const int*)mask)[zb * Sq + col] != 0;
            m1 = ((const int*)mask)[zb * Sq + col + 1] != 0;
        } else {
            m0 = ((const unsigned char*)mask)[zb * Sq + col] != 0;
            m1 = ((const unsigned char*)mask)[zb * Sq + col + 1] != 0;
        }
#pragma unroll
        for (int mt = 0; mt < 4; mt++)
#pragma unroll
            for (int h2 = 0; h2 < 2; h2++) {
                const int row = bm + wm + mt * 16 + g + h2 * 8;
                float v0 = m0 ? acc[mt][nt][h2 * 2 + 0] * 0.125f : NEG_INF;
                float v1 = m1 ? acc[mt][nt][h2 * 2 + 1] * 0.125f : NEG_INF;
                *(float2*)(attn + ((size_t)z * Sq + row) * Sq + col) = make_float2(v0, v1);
            }
    }
}

// ---------------------------------------------------------------------------
// Softmax — R12 exact (single barrier, flash rescale; 82.6% HBM roofline).
// ---------------------------------------------------------------------------
__global__ void __launch_bounds__(256) softmax_kernel(float* __restrict__ attn)
{
    const size_t row = blockIdx.x;
    float4* p = (float4*)(attn + row * Sq);
    const int tid = threadIdx.x, lane = tid & 31, wid = tid >> 5;

    float4 v0 = p[tid];
    float4 v1 = p[tid + 256];

    float tm = fmaxf(fmaxf(fmaxf(v0.x, v0.y), fmaxf(v0.z, v0.w)),
                     fmaxf(fmaxf(v1.x, v1.y), fmaxf(v1.z, v1.w)));
#pragma unroll
    for (int o = 16; o; o >>= 1) tm = fmaxf(tm, __shfl_xor_sync(~0u, tm, o));

    float e[8];
    e[0] = expf(v0.x - tm); e[1] = expf(v0.y - tm);
    e[2] = expf(v0.z - tm); e[3] = expf(v0.w - tm);
    e[4] = expf(v1.x - tm); e[5] = expf(v1.y - tm);
    e[6] = expf(v1.z - tm); e[7] = expf(v1.w - tm);
    float ts = e[0] + e[1] + e[2] + e[3] + e[4] + e[5] + e[6] + e[7];
#pragma unroll
    for (int o = 16; o; o >>= 1) ts += __shfl_xor_sync(~0u, ts, o);

    __shared__ float2 sm[8];
    if (lane == 0) sm[wid] = make_float2(tm, ts);
    __syncthreads();

    float m = sm[0].x;
#pragma unroll
    for (int j = 1; j < 8; j++) m = fmaxf(m, sm[j].x);
    float s = 0.f;
#pragma unroll
    for (int j = 0; j < 8; j++) s += sm[j].y * ex2((sm[j].x - m) * CLOG2E);

    const float r = ex2((tm - m) * CLOG2E) / s;
    v0 = make_float4(e[0] * r, e[1] * r, e[2] * r, e[3] * r);
    v1 = make_float4(e[4] * r, e[5] * r, e[6] * r, e[7] * r);
    p[tid]       = v0;
    p[tid + 256] = v1;
}

// ---------------------------------------------------------------------------
// Ctx — R12 exact: split-K=2, writes f32 partials to g_cpart.
// ---------------------------------------------------------------------------
#define SM_CTX 82944
__global__ void __launch_bounds__(256) ctx_kernel(const float* __restrict__ attn)
{
    constexpr int SA = 40, SB = 72;
    extern __shared__ char smc[];
    float* Pr = (float*)smc;
    float* Vr = (float*)(smc + 36864);
    __nv_bfloat16* Ah = (__nv_bfloat16*)(smc + 53248);
    __nv_bfloat16* Al = (__nv_bfloat16*)(smc + 63488);
    __nv_bfloat16* Bh = (__nv_bfloat16*)(smc + 73728);
    __nv_bfloat16* Bl = (__nv_bfloat16*)(smc + 78336);

    const int z = blockIdx.z, zb = z / Hn, zh = z % Hn;
    const int kz = blockIdx.x;
    const int kbase = kz * (Sq / 2);
    const float* P = attn + (size_t)z * Sq * Sq;
    const float* V = g_v + (size_t)z * Sq * DHd;
    float* Cp = g_cpart + (size_t)kz * NIN;
    const int bm = blockIdx.y * 128;

    const int tid = threadIdx.x, lane = tid & 31, warp = tid >> 5;
    const int wm = (warp >> 2) * 64;
    const int wn = (warp & 3) * 16;

    float acc[4][2][4];
#pragma unroll
    for (int i = 0; i < 4; i++)
#pragma unroll
        for (int j = 0; j < 2; j++)
#pragma unroll
            for (int q = 0; q < 4; q++) acc[i][j][q] = 0.f;

    const uint32_t aH = smem_u32(Ah), aL = smem_u32(Al);
    const uint32_t bH = smem_u32(Bh), bL = smem_u32(Bl);

    auto issue = [&](int s, int k0) {
        float* PrS = Pr + s * (128 * 36);
        float* VrS = Vr + s * (32 * 64);
#pragma unroll
        for (int r = 0; r < 4; r++) {
            const int idx = tid + r * 256;
            const int row = idx >> 3, ch = (idx & 7) * 4;
            CP16(smem_u32(PrS + row * 36 + ch),
                 P + (size_t)(bm + row) * Sq + k0 + ch);
        }
#pragma unroll
        for (int r = 0; r < 2; r++) {
            const int idx = tid + r * 256;
            const int row = idx >> 4, ch = (idx & 15) * 4;
            CP16(smem_u32(VrS + row * 64 + ch),
                 V + (size_t)(k0 + row) * DHd + ch);
        }
        CP_COMMIT();
    };

    const int NIT = (Sq / 2) / 32;
    issue(0, kbase);
    for (int it = 0; it < NIT; ++it) {
        const int s = it & 1;
        if (it + 1 < NIT) { issue(s ^ 1, kbase + (it + 1) * 32); CP_WAIT1(); }
        else              { CP_WAIT0(); }
        __syncthreads();

        float* PrS = Pr + s * (128 * 36);
        float* VrS = Vr + s * (32 * 64);
#pragma unroll
        for (int r = 0; r < 4; r++) {
            const int m  = (tid >> 3) + r * 32;
            const int kq = (tid & 7) * 4;
            float4 v = *(const float4*)(PrS + m * 36 + kq);
            split_to(v, &Ah[m * SA + kq], &Al[m * SA + kq]);
        }
#pragma unroll
        for (int r = 0; r < 2; r++) {
            const int kr = (tid >> 4) + r * 16;
            const int n4 = (tid & 15) * 4;
            float4 v = *(const float4*)(VrS + kr * 64 + n4);
            split_to(v, &Bh[kr * SB + n4], &Bl[kr * SB + n4]);
        }
        __syncthreads();

#pragma unroll
        for (int kk = 0; kk < 32; kk += 16) {
            uint32_t ah[4][4], al[4][4];
            const int arow = wm + (lane & 7) + ((lane >> 3) & 1) * 8;
            const int acol = kk + (lane >> 4) * 8;
#pragma unroll
            for (int mt = 0; mt < 4; mt++) {
                const uint32_t off = (uint32_t)(((arow + mt * 16) * SA + acol) * 2);
                ldm4(ah[mt], aH + off);
                ldm4(al[mt], aL + off);
            }
            uint32_t bh[2][2], bl[2][2];
            {
                const int brow = kk + (lane & 7) + ((lane >> 3) & 1) * 8;
                const int bcol = wn + (lane >> 4) * 8;
                const uint32_t off = (uint32_t)((brow * SB + bcol) * 2);
                uint32_t t[4];
                ldm4t(t, bH + off);
                bh[0][0] = t[0]; bh[0][1] = t[1];
                bh[1][0] = t[2]; bh[1][1] = t[3];
                ldm4t(t, bL + off);
                bl[0][0] = t[0]; bl[0][1] = t[1];
                bl[1][0] = t[2]; bl[1][1] = t[3];
            }
#pragma unroll
            for (int mt = 0; mt < 4; mt++)
#pragma unroll
                for (int nt = 0; nt < 2; nt++) {
                    mma_bf16(acc[mt][nt], ah[mt], bh[nt]);
                    mma_bf16(acc[mt][nt], ah[mt], bl[nt]);
                    mma_bf16(acc[mt][nt], al[mt], bh[nt]);
                }
        }
    }

    const int g = lane >> 2, t2 = (lane & 3) * 2;
#pragma unroll
    for (int mt = 0; mt < 4; mt++)
#pragma unroll
        for (int nt = 0; nt < 2; nt++) {
            const int col = wn + nt * 8 + t2;
#pragma unroll
            for (int h2 = 0; h2 < 2; h2++) {
                const int row = bm + wm + mt * 16 + g + h2 * 8;
                *(float2*)(Cp + ((size_t)zb * Sq + row) * Dm + zh * DHd + col)
                    = make_float2(acc[mt][nt][h2 * 2 + 0], acc[mt][nt][h2 * 2 + 1]);
            }
        }
}

// ---------------------------------------------------------------------------
// Launch. Inputs: qs ks vs mask Wq bq Wk bk Wv bv Wo bo.
// d_out: out [B,S,D] then attn [B,H,S,S].
// ---------------------------------------------------------------------------
extern "C" void kernel_launch(void* const* d_in, const int* in_sizes, int n_in,
                              void* d_out, int out_size)
{
    const float* qs = (const float*)d_in[0];
    const float* ks = (const float*)d_in[1];
    const float* vs = (const float*)d_in[2];
    const void*  mask = d_in[3];
    const float* Wq = (const float*)d_in[4];
    const float* bq = (const float*)d_in[5];
    const float* Wk = (const float*)d_in[6];
    const float* bk = (const float*)d_in[7];
    const float* Wv = (const float*)d_in[8];
    const float* bv = (const float*)d_in[9];
    const float* Wo = (const float*)d_in[10];
    const float* bo = (const float*)d_in[11];

    float* out  = (float*)d_out;
    float* attn = out + NIN;

    cudaFuncSetAttribute(proj_gemm<0>, cudaFuncAttributeMaxDynamicSharedMemorySize, SM_PROJ);
    cudaFuncSetAttribute(proj_gemm<1>, cudaFuncAttributeMaxDynamicSharedMemorySize, SM_PROJ);
    cudaFuncSetAttribute(ctx_kernel,  cudaFuncAttributeMaxDynamicSharedMemorySize, SM_CTX);

    float *gq, *gk, *gv, *gcp;
    cudaGetSymbolAddress((void**)&gq, g_q);
    cudaGetSymbolAddress((void**)&gk, g_k);
    cudaGetSymbolAddress((void**)&gv, g_v);
    cudaGetSymbolAddress((void**)&gcp, g_cpart);

    detect_mask_kernel<<<1, 256>>>((const unsigned char*)mask);

    ProjArgs pa;
    pa.A[0] = qs; pa.A[1] = ks; pa.A[2] = vs;
    pa.A2[0] = pa.A2[1] = pa.A2[2] = nullptr;
    pa.W[0] = Wq; pa.W[1] = Wk; pa.W[2] = Wv;
    pa.bias[0] = bq; pa.bias[1] = bk; pa.bias[2] = bv;
    pa.C[0] = gq; pa.C[1] = gk; pa.C[2] = gv;
    proj_gemm<0><<<dim3(Dm / 128, (Bz * Sq) / 128, 3), 256, SM_PROJ>>>(pa);

    scores_kernel<<<dim3(Sq / 128, Sq / 128, BH), 256>>>(mask, attn);

    softmax_kernel<<<(unsigned)((size_t)BH * Sq), 256>>>(attn);

    ctx_kernel<<<dim3(2, Sq / 128, BH), 256, SM_CTX>>>(attn);

    ProjArgs po;
    po.A[0] = gcp;            // ctx partial 0 (staged via cp.async)
    po.A2[0] = gcp + NIN;     // ctx partial 1 (fused add, L2-resident)
    po.W[0] = Wo; po.bias[0] = bo; po.C[0] = out;
    po.A[1] = po.A[2] = nullptr; po.A2[1] = po.A2[2] = nullptr;
    po.W[1] = po.W[2] = nullptr;
    po.bias[1] = po.bias[2] = nullptr; po.C[1] = po.C[2] = nullptr;
    proj_gemm<1><<<dim3(Dm / 128, (Bz * Sq) / 128, 1), 256, SM_PROJ>>>(po);
}

// round 15
// speedup vs baseline: 1.1084x; 1.1084x over previous
#include <cuda_runtime.h>
#include <cuda_bf16.h>
#include <stdint.h>
#include <math.h>

// Problem constants
#define Bz  2
#define Sq  2048
#define Dm  1024
#define Hn  16
#define DHd 64
#define BH  (Bz * Hn)
#define NIN ((size_t)Bz * Sq * Dm)
#define CLOG2E 1.4426950408889634f

// ---------------------------------------------------------------------------
// Scratch (allocation-free __device__ globals)
// ---------------------------------------------------------------------------
__device__ __align__(256) float g_q[(size_t)BH * Sq * DHd];
__device__ __align__(256) float g_k[(size_t)BH * Sq * DHd];
__device__ __align__(256) float g_v[(size_t)BH * Sq * DHd];
__device__ __align__(256) float g_ctx[NIN];
__device__ __align__(256) float g_cpart[2 * NIN];
__device__ int g_mask_is_int;

// ---------------------------------------------------------------------------
// Helpers
// ---------------------------------------------------------------------------
__device__ __forceinline__ uint32_t smem_u32(const void* p) {
    return (uint32_t)__cvta_generic_to_shared(p);
}
__device__ __forceinline__ void ldm4(uint32_t* r, uint32_t a) {
    asm volatile("ldmatrix.sync.aligned.m8n8.x4.shared.b16 {%0,%1,%2,%3},[%4];"
                 : "=r"(r[0]), "=r"(r[1]), "=r"(r[2]), "=r"(r[3]) : "r"(a));
}
__device__ __forceinline__ void ldm4t(uint32_t* r, uint32_t a) {
    asm volatile("ldmatrix.sync.aligned.m8n8.x4.trans.shared.b16 {%0,%1,%2,%3},[%4];"
                 : "=r"(r[0]), "=r"(r[1]), "=r"(r[2]), "=r"(r[3]) : "r"(a));
}
__device__ __forceinline__ void mma_bf16(float* c, const uint32_t* a, const uint32_t* b) {
    asm volatile(
        "mma.sync.aligned.m16n8k16.row.col.f32.bf16.bf16.f32 "
        "{%0,%1,%2,%3},{%4,%5,%6,%7},{%8,%9},{%0,%1,%2,%3};"
        : "+f"(c[0]), "+f"(c[1]), "+f"(c[2]), "+f"(c[3])
        : "r"(a[0]), "r"(a[1]), "r"(a[2]), "r"(a[3]), "r"(b[0]), "r"(b[1]));
}
// RN-based split (proven: rel_err ~2e-5)
__device__ __forceinline__ void split1(float x, __nv_bfloat16& h, __nv_bfloat16& l) {
    h = __float2bfloat16(x);
    l = __float2bfloat16(x - __bfloat162float(h));
}
__device__ __forceinline__ void split_to(float4 v, __nv_bfloat16* dh, __nv_bfloat16* dl) {
    __nv_bfloat16 h0, h1, h2, h3, l0, l1, l2, l3;
    split1(v.x, h0, l0); split1(v.y, h1, l1);
    split1(v.z, h2, l2); split1(v.w, h3, l3);
    *(__nv_bfloat162*)(dh)     = __nv_bfloat162{h0, h1};
    *(__nv_bfloat162*)(dh + 2) = __nv_bfloat162{h2, h3};
    *(__nv_bfloat162*)(dl)     = __nv_bfloat162{l0, l1};
    *(__nv_bfloat162*)(dl + 2) = __nv_bfloat162{l2, l3};
}
__device__ __forceinline__ float ex2(float x) {
    float y; asm("ex2.approx.f32 %0,%1;" : "=f"(y) : "f"(x)); return y;
}
#define CP16(dst, src) \
    asm volatile("cp.async.cg.shared.global [%0], [%1], 16;" \
                 :: "r"(dst), "l"(src) : "memory")
#define CP_COMMIT() asm volatile("cp.async.commit_group;" ::: "memory")
#define CP_WAIT1()  asm volatile("cp.async.wait_group 1;" ::: "memory")
#define CP_WAIT0()  asm volatile("cp.async.wait_group 0;" ::: "memory")

// ---------------------------------------------------------------------------
// Mask dtype detector
// ---------------------------------------------------------------------------
__global__ void detect_mask_kernel(const unsigned char* __restrict__ m) {
    __shared__ int any;
    if (threadIdx.x == 0) any = 0;
    __syncthreads();
    int local = 0;
    for (int i = threadIdx.x; i < Bz * Sq; i += blockDim.x)
        if ((i & 3) && m[i]) local = 1;
    if (local) atomicOr(&any, 1);
    __syncthreads();
    if (threadIdx.x == 0) g_mask_is_int = (any == 0) ? 1 : 0;
}

// ---------------------------------------------------------------------------
// Projection GEMM — R12 EXACT (no A2 path: proj is at the 128-reg/2-CTA edge).
// ---------------------------------------------------------------------------
struct ProjArgs {
    const float* A[3]; const float* W[3]; const float* bias[3]; float* C[3];
};
#define SM_PROJ 107520

template <int MODE>
__global__ void __launch_bounds__(256) proj_gemm(ProjArgs args)
{
    constexpr int SA = 40, SB = 136;
    extern __shared__ char smc[];
    float* Ar = (float*)smc;
    float* Br = (float*)(smc + 36864);
    __nv_bfloat16* Ah = (__nv_bfloat16*)(smc + 69632);
    __nv_bfloat16* Al = (__nv_bfloat16*)(smc + 79872);
    __nv_bfloat16* Bh = (__nv_bfloat16*)(smc + 90112);
    __nv_bfloat16* Bl = (__nv_bfloat16*)(smc + 98816);

    const int z = blockIdx.z;
    const float* A = args.A[z];
    const float* W = args.W[z];
    const float* bias = args.bias[z];
    float* C = args.C[z];

    const int tid = threadIdx.x, lane = tid & 31, warp = tid >> 5;
    const int wm = (warp >> 2) * 64;
    const int wn = (warp & 3) * 32;
    const int bm = blockIdx.y * 128;
    const int bn = blockIdx.x * 128;

    float acc[4][4][4];
#pragma unroll
    for (int i = 0; i < 4; i++)
#pragma unroll
        for (int j = 0; j < 4; j++)
#pragma unroll
            for (int q = 0; q < 4; q++) acc[i][j][q] = 0.f;

    const uint32_t aH = smem_u32(Ah), aL = smem_u32(Al);
    const uint32_t bH = smem_u32(Bh), bL = smem_u32(Bl);

    auto issue = [&](int s, int k0) {
        float* ArS = Ar + s * (128 * 36);
        float* BrS = Br + s * (32 * 128);
#pragma unroll
        for (int r = 0; r < 4; r++) {
            const int idx = tid + r * 256;
            const int row = idx >> 3, ch = (idx & 7) * 4;
            CP16(smem_u32(ArS + row * 36 + ch),
                 A + (size_t)(bm + row) * Dm + k0 + ch);
        }
#pragma unroll
        for (int r = 0; r < 4; r++) {
            const int idx = tid + r * 256;
            const int row = idx >> 5, ch = (idx & 31) * 4;
            CP16(smem_u32(BrS + row * 128 + ch),
                 W + (size_t)(k0 + row) * Dm + bn + ch);
        }
        CP_COMMIT();
    };

    issue(0, 0);
    for (int it = 0; it < Dm / 32; ++it) {
        const int s = it & 1;
        if (it + 1 < Dm / 32) { issue(s ^ 1, (it + 1) * 32); CP_WAIT1(); }
        else                  { CP_WAIT0(); }
        __syncthreads();

        float* ArS = Ar + s * (128 * 36);
        float* BrS = Br + s * (32 * 128);
#pragma unroll
        for (int r = 0; r < 4; r++) {
            const int m  = (tid >> 3) + r * 32;
            const int kq = (tid & 7) * 4;
            float4 v = *(const float4*)(ArS + m * 36 + kq);
            split_to(v, &Ah[m * SA + kq], &Al[m * SA + kq]);
        }
#pragma unroll
        for (int r = 0; r < 4; r++) {
            const int kr = (tid >> 5) + r * 8;
            const int n4 = (tid & 31) * 4;
            float4 v = *(const float4*)(BrS + kr * 128 + n4);
            split_to(v, &Bh[kr * SB + n4], &Bl[kr * SB + n4]);
        }
        __syncthreads();

#pragma unroll
        for (int kk = 0; kk < 32; kk += 16) {
            uint32_t ah[4][4], al[4][4];
            const int arow = wm + (lane & 7) + ((lane >> 3) & 1) * 8;
            const int acol = kk + (lane >> 4) * 8;
#pragma unroll
            for (int mt = 0; mt < 4; mt++) {
                const uint32_t off = (uint32_t)(((arow + mt * 16) * SA + acol) * 2);
                ldm4(ah[mt], aH + off);
                ldm4(al[mt], aL + off);
            }
            uint32_t bh[4][2], bl[4][2];
            const int brow = kk + (lane & 7) + ((lane >> 3) & 1) * 8;
#pragma unroll
            for (int sp = 0; sp < 2; sp++) {
                const int bcol = wn + sp * 16 + (lane >> 4) * 8;
                const uint32_t off = (uint32_t)((brow * SB + bcol) * 2);
                uint32_t t[4];
                ldm4t(t, bH + off);
                bh[2 * sp][0] = t[0]; bh[2 * sp][1] = t[1];
                bh[2 * sp + 1][0] = t[2]; bh[2 * sp + 1][1] = t[3];
                ldm4t(t, bL + off);
                bl[2 * sp][0] = t[0]; bl[2 * sp][1] = t[1];
                bl[2 * sp + 1][0] = t[2]; bl[2 * sp + 1][1] = t[3];
            }
#pragma unroll
            for (int mt = 0; mt < 4; mt++)
#pragma unroll
                for (int nt = 0; nt < 4; nt++) {
                    mma_bf16(acc[mt][nt], ah[mt], bh[nt]);
                    mma_bf16(acc[mt][nt], ah[mt], bl[nt]);
                    mma_bf16(acc[mt][nt], al[mt], bh[nt]);
                }
        }
    }

    const int g = lane >> 2, t2 = (lane & 3) * 2;
#pragma unroll
    for (int mt = 0; mt < 4; mt++)
#pragma unroll
        for (int nt = 0; nt < 4; nt++) {
            const int col = bn + wn + nt * 8 + t2;
#pragma unroll
            for (int h2 = 0; h2 < 2; h2++) {
                const int row = bm + wm + mt * 16 + g + h2 * 8;
                float c0 = acc[mt][nt][h2 * 2 + 0] + bias[col];
                float c1 = acc[mt][nt][h2 * 2 + 1] + bias[col + 1];
                if (MODE == 0) {
                    const int bb = row >> 11, ss = row & (Sq - 1);
                    const int hh = col >> 6,  dh = col & (DHd - 1);
                    *(float2*)(C + (((size_t)(bb * Hn + hh)) * Sq + ss) * DHd + dh)
                        = make_float2(c0, c1);
                } else {
                    *(float2*)(C + (size_t)row * Dm + col) = make_float2(c0, c1);
                }
            }
        }
}

// ---------------------------------------------------------------------------
// Scores — single-shot K=64 with DYNAMIC smem (73728 B): one fill (MLP 8),
// ONE sync, 192 MMAs. Accumulation order over kk = 0,16,32,48 preserved.
// ---------------------------------------------------------------------------
#define SM_SCORES (4 * 128 * 72 * 2)   // 73728
__global__ void __launch_bounds__(256) scores_kernel(
    const void* __restrict__ mask, float* __restrict__ attn)
{
    constexpr int SA = 72;
    extern __shared__ char smsc[];
    __nv_bfloat16* Ah = (__nv_bfloat16*)smsc;
    __nv_bfloat16* Al = Ah + 128 * SA;
    __nv_bfloat16* Bh = Al + 128 * SA;
    __nv_bfloat16* Bl = Bh + 128 * SA;

    const int z = blockIdx.z, zb = z / Hn;
    const float* q = g_q + (size_t)z * Sq * DHd;
    const float* k = g_k + (size_t)z * Sq * DHd;

    const int tid = threadIdx.x, lane = tid & 31, warp = tid >> 5;
    const int wm = (warp >> 2) * 64;
    const int wn = (warp & 3) * 32;
    const int bm = blockIdx.y * 128;
    const int bn = blockIdx.x * 128;

    float acc[4][4][4];
#pragma unroll
    for (int i = 0; i < 4; i++)
#pragma unroll
        for (int j = 0; j < 4; j++)
#pragma unroll
            for (int q2 = 0; q2 < 4; q2++) acc[i][j][q2] = 0.f;

    const uint32_t aH = smem_u32(Ah), aL = smem_u32(Al);
    const uint32_t bH = smem_u32(Bh), bL = smem_u32(Bl);

    // single fill: 128 rows x 64 cols for Q and K (8 float4 per thread)
#pragma unroll
    for (int r = 0; r < 8; r++) {
        const int idx = tid + r * 256;
        const int m = idx >> 4, kq = (idx & 15) * 4;
        float4 a = *(const float4*)(q + (size_t)(bm + m) * DHd + kq);
        split_to(a, &Ah[m * SA + kq], &Al[m * SA + kq]);
        float4 b = *(const float4*)(k + (size_t)(bn + m) * DHd + kq);
        split_to(b, &Bh[m * SA + kq], &Bl[m * SA + kq]);
    }
    __syncthreads();

#pragma unroll
    for (int kk = 0; kk < DHd; kk += 16) {
        uint32_t ah[4][4], al[4][4];
        const int arow = wm + (lane & 7) + ((lane >> 3) & 1) * 8;
        const int acol = kk + (lane >> 4) * 8;
#pragma unroll
        for (int mt = 0; mt < 4; mt++) {
            const uint32_t off = (uint32_t)(((arow + mt * 16) * SA + acol) * 2);
            ldm4(ah[mt], aH + off);
            ldm4(al[mt], aL + off);
        }
        uint32_t bh[4][2], bl[4][2];
#pragma unroll
        for (int sp = 0; sp < 2; sp++) {
            const int brow = wn + sp * 16 + (lane & 7) + ((lane >> 3) & 1) * 8;
            const int bcol = kk + (lane >> 4) * 8;
            const uint32_t off = (uint32_t)((brow * SA + bcol) * 2);
            uint32_t t[4];
            ldm4(t, bH + off);
            bh[2 * sp][0] = t[0]; bh[2 * sp + 1][0] = t[1];
            bh[2 * sp][1] = t[2]; bh[2 * sp + 1][1] = t[3];
            ldm4(t, bL + off);
            bl[2 * sp][0] = t[0]; bl[2 * sp + 1][0] = t[1];
            bl[2 * sp][1] = t[2]; bl[2 * sp + 1][1] = t[3];
        }
#pragma unroll
        for (int mt = 0; mt < 4; mt++)
#pragma unroll
            for (int nt = 0; nt < 4; nt++) {
                mma_bf16(acc[mt][nt], ah[mt], bh[nt]);
                mma_bf16(acc[mt][nt], ah[mt], bl[nt]);
                mma_bf16(acc[mt][nt], al[mt], bh[nt]);
            }
    }

    const int g = lane >> 2, t2 = (lane & 3) * 2;
    const int mint = g_mask_is_int;
    const float NEG_INF = __int_as_float(0xff800000);
#pragma unroll
    for (int nt = 0; nt < 4; nt++) {
        const int col = bn + wn + nt * 8 + t2;
        bool m0, m1;
        if (mint) {
            m0 = ((const int*)mask)[zb * Sq + col] != 0;
            m1 = ((const int*)mask)[zb * Sq + col + 1] != 0;
        } else {
            m0 = ((const unsigned char*)mask)[zb * Sq + col] != 0;
            m1 = ((const unsigned char*)mask)[zb * Sq + col + 1] != 0;
        }
#pragma unroll
        for (int mt = 0; mt < 4; mt++)
#pragma unroll
            for (int h2 = 0; h2 < 2; h2++) {
                const int row = bm + wm + mt * 16 + g + h2 * 8;
                float v0 = m0 ? acc[mt][nt][h2 * 2 + 0] * 0.125f : NEG_INF;
                float v1 = m1 ? acc[mt][nt][h2 * 2 + 1] * 0.125f : NEG_INF;
                *(float2*)(attn + ((size_t)z * Sq + row) * Sq + col) = make_float2(v0, v1);
            }
    }
}

// ---------------------------------------------------------------------------
// Softmax — R12 exact (single barrier, flash rescale; 82.6% HBM roofline).
// ---------------------------------------------------------------------------
__global__ void __launch_bounds__(256) softmax_kernel(float* __restrict__ attn)
{
    const size_t row = blockIdx.x;
    float4* p = (float4*)(attn + row * Sq);
    const int tid = threadIdx.x, lane = tid & 31, wid = tid >> 5;

    float4 v0 = p[tid];
    float4 v1 = p[tid + 256];

    float tm = fmaxf(fmaxf(fmaxf(v0.x, v0.y), fmaxf(v0.z, v0.w)),
                     fmaxf(fmaxf(v1.x, v1.y), fmaxf(v1.z, v1.w)));
#pragma unroll
    for (int o = 16; o; o >>= 1) tm = fmaxf(tm, __shfl_xor_sync(~0u, tm, o));

    float e[8];
    e[0] = expf(v0.x - tm); e[1] = expf(v0.y - tm);
    e[2] = expf(v0.z - tm); e[3] = expf(v0.w - tm);
    e[4] = expf(v1.x - tm); e[5] = expf(v1.y - tm);
    e[6] = expf(v1.z - tm); e[7] = expf(v1.w - tm);
    float ts = e[0] + e[1] + e[2] + e[3] + e[4] + e[5] + e[6] + e[7];
#pragma unroll
    for (int o = 16; o; o >>= 1) ts += __shfl_xor_sync(~0u, ts, o);

    __shared__ float2 sm[8];
    if (lane == 0) sm[wid] = make_float2(tm, ts);
    __syncthreads();

    float m = sm[0].x;
#pragma unroll
    for (int j = 1; j < 8; j++) m = fmaxf(m, sm[j].x);
    float s = 0.f;
#pragma unroll
    for (int j = 0; j < 8; j++) s += sm[j].y * ex2((sm[j].x - m) * CLOG2E);

    const float r = ex2((tm - m) * CLOG2E) / s;
    v0 = make_float4(e[0] * r, e[1] * r, e[2] * r, e[3] * r);
    v1 = make_float4(e[4] * r, e[5] * r, e[6] * r, e[7] * r);
    p[tid]       = v0;
    p[tid + 256] = v1;
}

// ---------------------------------------------------------------------------
// Ctx — R12 exact: split-K=2, writes f32 partials to g_cpart.
// ---------------------------------------------------------------------------
#define SM_CTX 82944
__global__ void __launch_bounds__(256) ctx_kernel(const float* __restrict__ attn)
{
    constexpr int SA = 40, SB = 72;
    extern __shared__ char smc[];
    float* Pr = (float*)smc;
    float* Vr = (float*)(smc + 36864);
    __nv_bfloat16* Ah = (__nv_bfloat16*)(smc + 53248);
    __nv_bfloat16* Al = (__nv_bfloat16*)(smc + 63488);
    __nv_bfloat16* Bh = (__nv_bfloat16*)(smc + 73728);
    __nv_bfloat16* Bl = (__nv_bfloat16*)(smc + 78336);

    const int z = blockIdx.z, zb = z / Hn, zh = z % Hn;
    const int kz = blockIdx.x;
    const int kbase = kz * (Sq / 2);
    const float* P = attn + (size_t)z * Sq * Sq;
    const float* V = g_v + (size_t)z * Sq * DHd;
    float* Cp = g_cpart + (size_t)kz * NIN;
    const int bm = blockIdx.y * 128;

    const int tid = threadIdx.x, lane = tid & 31, warp = tid >> 5;
    const int wm = (warp >> 2) * 64;
    const int wn = (warp & 3) * 16;

    float acc[4][2][4];
#pragma unroll
    for (int i = 0; i < 4; i++)
#pragma unroll
        for (int j = 0; j < 2; j++)
#pragma unroll
            for (int q = 0; q < 4; q++) acc[i][j][q] = 0.f;

    const uint32_t aH = smem_u32(Ah), aL = smem_u32(Al);
    const uint32_t bH = smem_u32(Bh), bL = smem_u32(Bl);

    auto issue = [&](int s, int k0) {
        float* PrS = Pr + s * (128 * 36);
        float* VrS = Vr + s * (32 * 64);
#pragma unroll
        for (int r = 0; r < 4; r++) {
            const int idx = tid + r * 256;
            const int row = idx >> 3, ch = (idx & 7) * 4;
            CP16(smem_u32(PrS + row * 36 + ch),
                 P + (size_t)(bm + row) * Sq + k0 + ch);
        }
#pragma unroll
        for (int r = 0; r < 2; r++) {
            const int idx = tid + r * 256;
            const int row = idx >> 4, ch = (idx & 15) * 4;
            CP16(smem_u32(VrS + row * 64 + ch),
                 V + (size_t)(k0 + row) * DHd + ch);
        }
        CP_COMMIT();
    };

    const int NIT = (Sq / 2) / 32;
    issue(0, kbase);
    for (int it = 0; it < NIT; ++it) {
        const int s = it & 1;
        if (it + 1 < NIT) { issue(s ^ 1, kbase + (it + 1) * 32); CP_WAIT1(); }
        else              { CP_WAIT0(); }
        __syncthreads();

        float* PrS = Pr + s * (128 * 36);
        float* VrS = Vr + s * (32 * 64);
#pragma unroll
        for (int r = 0; r < 4; r++) {
            const int m  = (tid >> 3) + r * 32;
            const int kq = (tid & 7) * 4;
            float4 v = *(const float4*)(PrS + m * 36 + kq);
            split_to(v, &Ah[m * SA + kq], &Al[m * SA + kq]);
        }
#pragma unroll
        for (int r = 0; r < 2; r++) {
            const int kr = (tid >> 4) + r * 16;
            const int n4 = (tid & 15) * 4;
            float4 v = *(const float4*)(VrS + kr * 64 + n4);
            split_to(v, &Bh[kr * SB + n4], &Bl[kr * SB + n4]);
        }
        __syncthreads();

#pragma unroll
        for (int kk = 0; kk < 32; kk += 16) {
            uint32_t ah[4][4], al[4][4];
            const int arow = wm + (lane & 7) + ((lane >> 3) & 1) * 8;
            const int acol = kk + (lane >> 4) * 8;
#pragma unroll
            for (int mt = 0; mt < 4; mt++) {
                const uint32_t off = (uint32_t)(((arow + mt * 16) * SA + acol) * 2);
                ldm4(ah[mt], aH + off);
                ldm4(al[mt], aL + off);
            }
            uint32_t bh[2][2], bl[2][2];
            {
                const int brow = kk + (lane & 7) + ((lane >> 3) & 1) * 8;
                const int bcol = wn + (lane >> 4) * 8;
                const uint32_t off = (uint32_t)((brow * SB + bcol) * 2);
                uint32_t t[4];
                ldm4t(t, bH + off);
                bh[0][0] = t[0]; bh[0][1] = t[1];
                bh[1][0] = t[2]; bh[1][1] = t[3];
                ldm4t(t, bL + off);
                bl[0][0] = t[0]; bl[0][1] = t[1];
                bl[1][0] = t[2]; bl[1][1] = t[3];
            }
#pragma unroll
            for (int mt = 0; mt < 4; mt++)
#pragma unroll
                for (int nt = 0; nt < 2; nt++) {
                    mma_bf16(acc[mt][nt], ah[mt], bh[nt]);
                    mma_bf16(acc[mt][nt], ah[mt], bl[nt]);
                    mma_bf16(acc[mt][nt], al[mt], bh[nt]);
                }
        }
    }

    const int g = lane >> 2, t2 = (lane & 3) * 2;
#pragma unroll
    for (int mt = 0; mt < 4; mt++)
#pragma unroll
        for (int nt = 0; nt < 2; nt++) {
            const int col = wn + nt * 8 + t2;
#pragma unroll
            for (int h2 = 0; h2 < 2; h2++) {
                const int row = bm + wm + mt * 16 + g + h2 * 8;
                *(float2*)(Cp + ((size_t)zb * Sq + row) * Dm + zh * DHd + col)
                    = make_float2(acc[mt][nt][h2 * 2 + 0], acc[mt][nt][h2 * 2 + 1]);
            }
        }
}

// ---------------------------------------------------------------------------
// Deterministic pairwise reduce of the two ctx K-halves (R12 exact).
// ---------------------------------------------------------------------------
__global__ void __launch_bounds__(256) ctx_reduce_kernel() {
    const size_t i = (size_t)blockIdx.x * 256 + threadIdx.x;
    float4 a = ((const float4*)g_cpart)[i];
    float4 b = ((const float4*)(g_cpart + NIN))[i];
    ((float4*)g_ctx)[i] = make_float4(a.x + b.x, a.y + b.y, a.z + b.z, a.w + b.w);
}

// ---------------------------------------------------------------------------
// Launch. Inputs: qs ks vs mask Wq bq Wk bk Wv bv Wo bo.
// d_out: out [B,S,D] then attn [B,H,S,S].
// ---------------------------------------------------------------------------
extern "C" void kernel_launch(void* const* d_in, const int* in_sizes, int n_in,
                              void* d_out, int out_size)
{
    const float* qs = (const float*)d_in[0];
    const float* ks = (const float*)d_in[1];
    const float* vs = (const float*)d_in[2];
    const void*  mask = d_in[3];
    const float* Wq = (const float*)d_in[4];
    const float* bq = (const float*)d_in[5];
    const float* Wk = (const float*)d_in[6];
    const float* bk = (const float*)d_in[7];
    const float* Wv = (const float*)d_in[8];
    const float* bv = (const float*)d_in[9];
    const float* Wo = (const float*)d_in[10];
    const float* bo = (const float*)d_in[11];

    float* out  = (float*)d_out;
    float* attn = out + NIN;

    cudaFuncSetAttribute(proj_gemm<0>, cudaFuncAttributeMaxDynamicSharedMemorySize, SM_PROJ);
    cudaFuncSetAttribute(proj_gemm<1>, cudaFuncAttributeMaxDynamicSharedMemorySize, SM_PROJ);
    cudaFuncSetAttribute(scores_kernel, cudaFuncAttributeMaxDynamicSharedMemorySize, SM_SCORES);
    cudaFuncSetAttribute(ctx_kernel,  cudaFuncAttributeMaxDynamicSharedMemorySize, SM_CTX);

    float *gq, *gk, *gv, *gctx;
    cudaGetSymbolAddress((void**)&gq, g_q);
    cudaGetSymbolAddress((void**)&gk, g_k);
    cudaGetSymbolAddress((void**)&gv, g_v);
    cudaGetSymbolAddress((void**)&gctx, g_ctx);

    detect_mask_kernel<<<1, 256>>>((const unsigned char*)mask);

    ProjArgs pa;
    pa.A[0] = qs; pa.A[1] = ks; pa.A[2] = vs;
    pa.W[0] = Wq; pa.W[1] = Wk; pa.W[2] = Wv;
    pa.bias[0] = bq; pa.bias[1] = bk; pa.bias[2] = bv;
    pa.C[0] = gq; pa.C[1] = gk; pa.C[2] = gv;
    proj_gemm<0><<<dim3(Dm / 128, (Bz * Sq) / 128, 3), 256, SM_PROJ>>>(pa);

    scores_kernel<<<dim3(Sq / 128, Sq / 128, BH), 256, SM_SCORES>>>(mask, attn);

    softmax_kernel<<<(unsigned)((size_t)BH * Sq), 256>>>(attn);

    ctx_kernel<<<dim3(2, Sq / 128, BH), 256, SM_CTX>>>(attn);

    ctx_reduce_kernel<<<(unsigned)(NIN / 4 / 256), 256>>>();

    ProjArgs po;
    po.A[0] = gctx; po.W[0] = Wo; po.bias[0] = bo; po.C[0] = out;
    po.A[1] = po.A[2] = nullptr; po.W[1] = po.W[2] = nullptr;
    po.bias[1] = po.bias[2] = nullptr; po.C[1] = po.C[2] = nullptr;
    proj_gemm<1><<<dim3(Dm / 128, (Bz * Sq) / 128, 1), 256, SM_PROJ>>>(po);
}